// round 3
// baseline (speedup 1.0000x reference)
#include <cuda_runtime.h>

#define LSEQ 512
#define BSZ 1024
#define NTAG 64
#define START_TAG 62
#define END_TAG 63

typedef unsigned long long ull;

// ---- packed f32x2 helpers (Blackwell FFMA2: only reachable via PTX) ----
__device__ __forceinline__ ull pack2(float lo, float hi) {
    ull d;
    asm("mov.b64 %0, {%1, %2};" : "=l"(d) : "f"(lo), "f"(hi));
    return d;
}
__device__ __forceinline__ void unpack2(ull v, float& lo, float& hi) {
    asm("mov.b64 {%0, %1}, %2;" : "=f"(lo), "=f"(hi) : "l"(v));
}
__device__ __forceinline__ ull fma2(ull a, ull b, ull c) {
    ull d;
    asm("fma.rn.f32x2 %0, %1, %2, %3;" : "=l"(d) : "l"(a), "l"(b), "l"(c));
    return d;
}
__device__ __forceinline__ ull add2(ull a, ull b) {
    ull d;
    asm("add.rn.f32x2 %0, %1, %2;" : "=l"(d) : "l"(a), "l"(b));
    return d;
}

// ============================================================================
// Fused CRF kernel. ONE WARP PER BATCH, 32-thread blocks (grid=1024 for best
// SM load balance: 1024 warps / 148 SMs ~= 7/SM).
//
// Linear-domain forward: v' = (E @ v) * exp(feat) * scale, running log-offset
// c. Lane owns output tags (2*lane, 2*lane+1); E rows in 128 registers.
// Latency engineering:
//  - 4-deep register pipeline on the shared-memory v loads (no LDS->FMA stall)
//  - exp(feat)*scale hoisted before the MV (MUFU hidden under FMA chain)
//  - DEFERRED renorm: every 4th step, butterfly-max/log/rcp run AFTER the
//    store, and 1/hi is folded into the NEXT step's exp(feat) multiply ->
//    the whole renorm overlaps the next step's MV (off the critical path).
//  - ping-pong v buffers, single __syncwarp per step
//  - feats/mask prefetched 4 steps ahead in a register ring
// Realpath (gold score) fused as a per-warp tail, lanes split over L.
// ============================================================================
__global__ __launch_bounds__(32) void crf_fused_kernel(
    const float* __restrict__ feats,
    const int*   __restrict__ tags,
    const float* __restrict__ mask,
    const float* __restrict__ transition,
    float* __restrict__ out)
{
    __shared__ __align__(16) float vsh[2][NTAG];
    const int lane = threadIdx.x;
    const int b = blockIdx.x;
    const int t0 = 2 * lane;
    const int t1 = t0 + 1;

    // e0[i] = (E[t0,2i], E[t0,2i+1]),  e1[i] = (E[t1,2i], E[t1,2i+1])
    ull e0[32], e1[32];
#pragma unroll
    for (int i = 0; i < 32; ++i) {
        e0[i] = pack2(__expf(__ldg(transition + t0 * NTAG + 2 * i)),
                      __expf(__ldg(transition + t0 * NTAG + 2 * i + 1)));
        e1[i] = pack2(__expf(__ldg(transition + t1 * NTAG + 2 * i)),
                      __expf(__ldg(transition + t1 * NTAG + 2 * i + 1)));
    }

    // alpha0 = NEG except START=0  ->  v = one-hot(START), c = 0
    float myv0 = (t0 == START_TAG) ? 1.0f : 0.0f;
    float myv1 = (t1 == START_TAG) ? 1.0f : 0.0f;
    ((float2*)vsh[0])[lane] = make_float2(myv0, myv1);
    float c = 0.0f;
    float scale = 1.0f;   // pending renorm scale, applied on the NEXT update
    __syncwarp();

    // 4-deep prefetch ring for feats/mask
    const float* fptr = feats + (size_t)b * NTAG + t0;
    float2 fr[4];
    float  mr[4];
#pragma unroll
    for (int u = 0; u < 4; ++u) {
        fr[u] = *(const float2*)(fptr + (size_t)u * (BSZ * NTAG));
        mr[u] = __ldg(mask + u * BSZ + b);
    }

    for (int l4 = 0; l4 < LSEQ; l4 += 4) {
#pragma unroll
        for (int u = 0; u < 4; ++u) {
            const int l = l4 + u;
            const float2 f = fr[u];
            const float  m = mr[u];
            int ln = l + 4;
            if (ln > LSEQ - 1) ln = LSEQ - 1;
            fr[u] = *(const float2*)(fptr + (size_t)ln * (BSZ * NTAG));
            mr[u] = __ldg(mask + ln * BSZ + b);

            // hoisted: independent of v -> MUFU latency hidden under MV
            const float efx = __expf(f.x) * scale;
            const float efy = __expf(f.y) * scale;

            // v' = E @ v : 4 f32x2 chains, LDS pipelined 4 deep in registers
            const ulonglong2* vp = (const ulonglong2*)vsh[l & 1];
            ull ae0 = 0ull, ae1 = 0ull, ao0 = 0ull, ao1 = 0ull;
            ulonglong2 w[4];
#pragma unroll
            for (int j = 0; j < 4; ++j) w[j] = vp[j];
#pragma unroll
            for (int i = 0; i < 16; ++i) {
                const ulonglong2 cur = w[i & 3];
                if (i < 12) w[i & 3] = vp[i + 4];
                ae0 = fma2(e0[2 * i],     cur.x, ae0);
                ae1 = fma2(e1[2 * i],     cur.x, ae1);
                ao0 = fma2(e0[2 * i + 1], cur.y, ao0);
                ao1 = fma2(e1[2 * i + 1], cur.y, ao1);
            }
            const ull s0 = add2(ae0, ao0);
            const ull s1 = add2(ae1, ao1);
            float s0l, s0h, s1l, s1h;
            unpack2(s0, s0l, s0h);
            unpack2(s1, s1l, s1h);
            float v0n = (s0l + s0h) * efx;
            float v1n = (s1l + s1h) * efy;

            // masked step keeps old v, but pending scale must still apply
            if (m == 0.0f) { v0n = myv0 * scale; v1n = myv1 * scale; }

            myv0 = v0n;
            myv1 = v1n;
            ((float2*)vsh[(l & 1) ^ 1])[lane] = make_float2(v0n, v1n);
            __syncwarp();

            if (u == 3) {
                // deferred renorm: runs concurrently with next step's MV
                float hi = fmaxf(v0n, v1n);
#pragma unroll
                for (int o = 16; o > 0; o >>= 1)
                    hi = fmaxf(hi, __shfl_xor_sync(0xffffffffu, hi, o));
                c += __logf(hi);
                scale = __fdividef(1.0f, hi);
            } else {
                scale = 1.0f;
            }
        }
    }

    // allpath = c + log( scale_pending * sum_t v[t] * exp(transition[END][t]) )
    float s = myv0 * __expf(__ldg(transition + END_TAG * NTAG + t0))
            + myv1 * __expf(__ldg(transition + END_TAG * NTAG + t1));
#pragma unroll
    for (int o = 16; o > 0; o >>= 1)
        s += __shfl_xor_sync(0xffffffffu, s, o);
    const float allpath = c + __logf(s * scale);

    // ---- realpath tail: lanes split L (16 each), independent gathers ----
    float rsum = 0.0f, rlen = 0.0f;
#pragma unroll
    for (int i = 0; i < 16; ++i) {
        const int l = lane + 32 * i;
        int tag  = __ldg(tags + l * BSZ + b);
        int prev = (l == 0) ? START_TAG : __ldg(tags + (l - 1) * BSZ + b);
        float m  = __ldg(mask + l * BSZ + b);
        float emit = __ldg(feats + ((size_t)l * BSZ + b) * NTAG + tag);
        float tr   = __ldg(transition + tag * NTAG + prev);
        rsum += (emit + tr) * m;
        rlen += m;
    }
#pragma unroll
    for (int o = 16; o > 0; o >>= 1) {
        rsum += __shfl_xor_sync(0xffffffffu, rsum, o);
        rlen += __shfl_xor_sync(0xffffffffu, rlen, o);
    }
    if (lane == 0) {
        int length = (int)(rlen + 0.5f);
        int last = (length > 0) ? __ldg(tags + (length - 1) * BSZ + b) : START_TAG;
        float real = rsum + __ldg(transition + END_TAG * NTAG + last);
        out[b] = allpath - real;
    }
}

extern "C" void kernel_launch(void* const* d_in, const int* in_sizes, int n_in,
                              void* d_out, int out_size) {
    const float* feats      = (const float*)d_in[0];
    const int*   tags       = (const int*)  d_in[1];
    const float* mask       = (const float*)d_in[2];
    const float* transition = (const float*)d_in[3];
    float* out = (float*)d_out;

    crf_fused_kernel<<<BSZ, 32>>>(feats, tags, mask, transition, out);
}

// round 4
// speedup vs baseline: 1.1240x; 1.1240x over previous
#include <cuda_runtime.h>

#define LSEQ 512
#define BSZ 1024
#define NTAG 64
#define START_TAG 62
#define END_TAG 63

typedef unsigned long long ull;

// ---- packed f32x2 helpers (Blackwell FFMA2: only reachable via PTX) ----
__device__ __forceinline__ ull pack2(float lo, float hi) {
    ull d;
    asm("mov.b64 %0, {%1, %2};" : "=l"(d) : "f"(lo), "f"(hi));
    return d;
}
__device__ __forceinline__ void unpack2(ull v, float& lo, float& hi) {
    asm("mov.b64 {%0, %1}, %2;" : "=f"(lo), "=f"(hi) : "l"(v));
}
__device__ __forceinline__ ull fma2(ull a, ull b, ull c) {
    ull d;
    asm("fma.rn.f32x2 %0, %1, %2, %3;" : "=l"(d) : "l"(a), "l"(b), "l"(c));
    return d;
}
__device__ __forceinline__ ull add2(ull a, ull b) {
    ull d;
    asm("add.rn.f32x2 %0, %1, %2;" : "=l"(d) : "l"(a), "l"(b));
    return d;
}

// ============================================================================
// Fused CRF kernel. TWO WARPS PER BATCH (64-thread block, grid = 1024).
// Thread tid owns output tag t == tid. Each thread holds its E row packed as
// 32 f32x2 pairs (64 regs). Linear-domain forward v' = (E @ v) * exp(f) with
// running log-offset c; renorm every 4 steps, branch-free and deferred:
//   - step l%4==3: per-warp butterfly max of new v -> maxsh[warp]
//   - step l%4==0: hi = max(maxsh[0],maxsh[1]); scale=1/hi; c += log(hi),
//     folded into exp(f)*scale (maxsh preinit to 1.0 => first step no-op,
//     pending max at exit carries no obligation).
// Per step: 16 broadcast LDS.128 (4-deep reg pipeline), 32 FFMA2 in 4 chains
// of depth 8, one STS.32, one bar.sync(nw=2).
// 1024 blocks / 148 SMs ~= 7 -> launch_bounds(64,7) keeps one full wave.
// Realpath (gold score) fused as a block tail.
// ============================================================================
__global__ void __launch_bounds__(64, 7) crf_fused_kernel(
    const float* __restrict__ feats,
    const int*   __restrict__ tags,
    const float* __restrict__ mask,
    const float* __restrict__ transition,
    float* __restrict__ out)
{
    __shared__ __align__(16) float vsh[2][NTAG];
    __shared__ float maxsh[2];
    __shared__ float redsh[6];   // [warp sums of end-score][rsum][rlen]

    const int tid  = threadIdx.x;
    const int w    = tid >> 5;
    const int lane = tid & 31;
    const int b    = blockIdx.x;
    const int t    = tid;           // output tag owned by this thread

    // E2[i] = ( exp(T[t,2i]), exp(T[t,2i+1]) )
    ull E2[32];
#pragma unroll
    for (int i = 0; i < 32; ++i) {
        E2[i] = pack2(__expf(__ldg(transition + t * NTAG + 2 * i)),
                      __expf(__ldg(transition + t * NTAG + 2 * i + 1)));
    }

    // v0 = one-hot(START), c = 0
    float myv = (t == START_TAG) ? 1.0f : 0.0f;
    vsh[0][t] = myv;
    if (tid < 2) maxsh[tid] = 1.0f;   // first renorm-consume is a no-op
    float c = 0.0f;
    __syncthreads();

    // 4-deep prefetch ring: this thread's feat stream + uniform mask stream
    const float* fptr = feats + (size_t)b * NTAG + t;
    float fr[4], mr[4];
#pragma unroll
    for (int u = 0; u < 4; ++u) {
        fr[u] = __ldg(fptr + (size_t)u * (BSZ * NTAG));
        mr[u] = __ldg(mask + u * BSZ + b);
    }

    for (int l4 = 0; l4 < LSEQ; l4 += 4) {
#pragma unroll
        for (int u = 0; u < 4; ++u) {
            const int l = l4 + u;
            const float f = fr[u];
            const float m = mr[u];
            int ln = l + 4;
            if (ln > LSEQ - 1) ln = LSEQ - 1;
            fr[u] = __ldg(fptr + (size_t)ln * (BSZ * NTAG));
            mr[u] = __ldg(mask + ln * BSZ + b);

            // consume deferred renorm (u==0); branch-free via maxsh preinit
            float scale = 1.0f;
            if (u == 0) {
                const float hi = fmaxf(maxsh[0], maxsh[1]);
                scale = __fdividef(1.0f, hi);
                c += __logf(hi);
            }
            const float ef = __expf(f) * scale;   // independent of v: hidden

            // v'[t] = sum_p E[t,p] * v[p] ; 4 f32x2 chains of depth 8
            const ulonglong2* vp = (const ulonglong2*)vsh[l & 1];
            ull a0 = 0ull, a1 = 0ull, a2 = 0ull, a3 = 0ull;
            ulonglong2 wr[4];
#pragma unroll
            for (int j = 0; j < 4; ++j) wr[j] = vp[j];
#pragma unroll
            for (int i = 0; i < 16; ++i) {
                const ulonglong2 cur = wr[i & 3];
                if (i < 12) wr[i & 3] = vp[i + 4];
                if (i & 1) {
                    a2 = fma2(E2[2 * i],     cur.x, a2);
                    a3 = fma2(E2[2 * i + 1], cur.y, a3);
                } else {
                    a0 = fma2(E2[2 * i],     cur.x, a0);
                    a1 = fma2(E2[2 * i + 1], cur.y, a1);
                }
            }
            const ull s2 = add2(add2(a0, a2), add2(a1, a3));
            float sl, sh;
            unpack2(s2, sl, sh);
            float vnew = (sl + sh) * ef;

            // masked step keeps old v (pending scale still applies)
            if (m == 0.0f) vnew = myv * scale;

            myv = vnew;
            vsh[(l & 1) ^ 1][t] = vnew;

            if (u == 3) {   // produce next renorm factor (consumed at u==0)
                float hi = vnew;
#pragma unroll
                for (int o = 16; o > 0; o >>= 1)
                    hi = fmaxf(hi, __shfl_xor_sync(0xffffffffu, hi, o));
                if (lane == 0) maxsh[w] = hi;
            }
            __syncthreads();
        }
    }

    // allpath = c + log( sum_t v[t] * exp(T[END,t]) )  (no pending obligation)
    float s = myv * __expf(__ldg(transition + END_TAG * NTAG + t));
#pragma unroll
    for (int o = 16; o > 0; o >>= 1)
        s += __shfl_xor_sync(0xffffffffu, s, o);
    if (lane == 0) redsh[w] = s;

    // ---- realpath tail: 64 threads split L (8 each), independent gathers --
    float rsum = 0.0f, rlen = 0.0f;
#pragma unroll
    for (int i = 0; i < 8; ++i) {
        const int l = tid + 64 * i;
        int tag  = __ldg(tags + l * BSZ + b);
        int prev = (l == 0) ? START_TAG : __ldg(tags + (l - 1) * BSZ + b);
        float m  = __ldg(mask + l * BSZ + b);
        float emit = __ldg(feats + ((size_t)l * BSZ + b) * NTAG + tag);
        float tr   = __ldg(transition + tag * NTAG + prev);
        rsum += (emit + tr) * m;
        rlen += m;
    }
#pragma unroll
    for (int o = 16; o > 0; o >>= 1) {
        rsum += __shfl_xor_sync(0xffffffffu, rsum, o);
        rlen += __shfl_xor_sync(0xffffffffu, rlen, o);
    }
    if (lane == 0) { redsh[2 + w] = rsum; redsh[4 + w] = rlen; }
    __syncthreads();

    if (tid == 0) {
        const float allpath = c + __logf(redsh[0] + redsh[1]);
        const float rs = redsh[2] + redsh[3];
        const int length = (int)(redsh[4] + redsh[5] + 0.5f);
        const int last = (length > 0) ? __ldg(tags + (length - 1) * BSZ + b)
                                      : START_TAG;
        const float real = rs + __ldg(transition + END_TAG * NTAG + last);
        out[b] = allpath - real;
    }
}

extern "C" void kernel_launch(void* const* d_in, const int* in_sizes, int n_in,
                              void* d_out, int out_size) {
    const float* feats      = (const float*)d_in[0];
    const int*   tags       = (const int*)  d_in[1];
    const float* mask       = (const float*)d_in[2];
    const float* transition = (const float*)d_in[3];
    float* out = (float*)d_out;

    crf_fused_kernel<<<BSZ, 64>>>(feats, tags, mask, transition, out);
}